// round 10
// baseline (speedup 1.0000x reference)
#include <cuda_runtime.h>
#include <cuda_bf16.h>
#include <cuda_fp16.h>
#include <cstdint>

#define N_NODES 100000
#define N_EDGES 1600000
#define D_IN 128
#define D_HID 128
#define N_CLASSES 64

// ---------------- device scratch (no dynamic alloc) ----------------
// Single fp16 copy of every activation; bf16 hi/lo produced on the fly in GEMMs.
__device__ __align__(16) __half g_feat16[(size_t)N_NODES * D_IN];
__device__ __align__(16) __half g_agg16 [(size_t)N_NODES * D_HID];
__device__ __align__(16) __half g_h1_16 [(size_t)N_NODES * D_HID];
__device__ __align__(16) __half g_h2_16 [(size_t)N_NODES * D_HID];
// transposed split weights, B[n][k]  (K=256 for layers, 128 for out) — exact split of fp32
__device__ __align__(16) __nv_bfloat16 g_B1_hi[128 * 256];
__device__ __align__(16) __nv_bfloat16 g_B1_lo[128 * 256];
__device__ __align__(16) __nv_bfloat16 g_B2_hi[128 * 256];
__device__ __align__(16) __nv_bfloat16 g_B2_lo[128 * 256];
__device__ __align__(16) __nv_bfloat16 g_Bo_hi[64 * 128];
__device__ __align__(16) __nv_bfloat16 g_Bo_lo[64 * 128];
// CSR (g_esrc padded by 8 zero entries so the predicated gather can over-read)
__device__ float    g_inv [N_NODES];
__device__ unsigned g_ideg[N_NODES];
__device__ unsigned g_off [N_NODES + 1];
__device__ unsigned g_cur [N_NODES];
__device__ int      g_esrc[N_EDGES + 8];

// ---------------- helpers ----------------
__device__ __forceinline__ uint32_t smem_to_u32(const void* p) {
    uint32_t a;
    asm("{ .reg .u64 t; cvta.to.shared.u64 t, %1; cvt.u32.u64 %0, t; }" : "=r"(a) : "l"(p));
    return a;
}

__device__ __forceinline__ void ldsm_x4(uint32_t addr, uint32_t* r) {
    asm volatile("ldmatrix.sync.aligned.m8n8.x4.shared.b16 {%0,%1,%2,%3}, [%4];"
                 : "=r"(r[0]), "=r"(r[1]), "=r"(r[2]), "=r"(r[3]) : "r"(addr));
}

__device__ __forceinline__ void mma16816(float* c, const uint32_t* a,
                                         uint32_t b0, uint32_t b1) {
    asm volatile("mma.sync.aligned.m16n8k16.row.col.f32.bf16.bf16.f32 "
                 "{%0,%1,%2,%3}, {%4,%5,%6,%7}, {%8,%9}, {%0,%1,%2,%3};"
                 : "+f"(c[0]), "+f"(c[1]), "+f"(c[2]), "+f"(c[3])
                 : "r"(a[0]), "r"(a[1]), "r"(a[2]), "r"(a[3]), "r"(b0), "r"(b1));
}

__device__ __forceinline__ void split_bf16(float v, __nv_bfloat16& hi, __nv_bfloat16& lo) {
    hi = __float2bfloat16(v);
    lo = __float2bfloat16(v - __bfloat162float(hi));
}

// 8 fp16 (uint4) -> 8 bf16 hi (uint4) + 8 bf16 lo (uint4). Exact for fp16 inputs.
__device__ __forceinline__ void cvt_h8_split(const uint4& raw, uint4& hi4, uint4& lo4) {
    const __half2* hp = reinterpret_cast<const __half2*>(&raw);
    uint32_t H[4], L[4];
#pragma unroll
    for (int i = 0; i < 4; ++i) {
        float2 f = __half22float2(hp[i]);
        __nv_bfloat16 h0, l0, h1, l1;
        split_bf16(f.x, h0, l0);
        split_bf16(f.y, h1, l1);
        __nv_bfloat162 Hb; Hb.x = h0; Hb.y = h1;
        __nv_bfloat162 Lb; Lb.x = l0; Lb.y = l1;
        H[i] = *reinterpret_cast<uint32_t*>(&Hb);
        L[i] = *reinterpret_cast<uint32_t*>(&Lb);
    }
    hi4 = make_uint4(H[0], H[1], H[2], H[3]);
    lo4 = make_uint4(L[0], L[1], L[2], L[3]);
}

// ---------------- CSR build ----------------
__global__ void zero_ideg_kernel() {
    int i = blockIdx.x * blockDim.x + threadIdx.x;
    if (i < N_NODES) g_ideg[i] = 0u;
}
__global__ void deg_kernel(const int* __restrict__ dst) {
    int e = blockIdx.x * blockDim.x + threadIdx.x;
    if (e < N_EDGES) atomicAdd(&g_ideg[dst[e]], 1u);
}
__global__ __launch_bounds__(1024)
void scan_kernel() {
    __shared__ unsigned sm[1024];
    const int t  = threadIdx.x;
    const int CH = (N_NODES + 1023) / 1024;
    int lo = t * CH;
    int hi = lo + CH; if (hi > N_NODES) hi = N_NODES;
    if (lo > N_NODES) lo = N_NODES;
    unsigned sum = 0;
    for (int i = lo; i < hi; ++i) sum += g_ideg[i];
    sm[t] = sum;
    __syncthreads();
    for (int d = 1; d < 1024; d <<= 1) {
        unsigned u = (t >= d) ? sm[t - d] : 0u;
        __syncthreads();
        sm[t] += u;
        __syncthreads();
    }
    unsigned off = sm[t] - sum;
    for (int i = lo; i < hi; ++i) {
        unsigned d = g_ideg[i];
        g_off[i] = off;
        g_cur[i] = off;
        g_inv[i] = 1.0f / fmaxf((float)d, 1.0f);
        off += d;
    }
    if (t == 1023) g_off[N_NODES] = sm[1023];
}
__global__ void fill_kernel(const int* __restrict__ src, const int* __restrict__ dst) {
    int e = blockIdx.x * blockDim.x + threadIdx.x;
    if (e < N_EDGES) {
        unsigned p = atomicAdd(&g_cur[dst[e]], 1u);
        g_esrc[p] = src[e];
    }
}

// ---------------- input/weight prep ----------------
__global__ void fconv_kernel(const float* __restrict__ f) {
    unsigned i = blockIdx.x * blockDim.x + threadIdx.x;   // over N_NODES*32 float4 units
    if (i >= (unsigned)N_NODES * 32u) return;
    float4 v = reinterpret_cast<const float4*>(f)[i];
    __half2 q0 = __floats2half2_rn(v.x, v.y);
    __half2 q1 = __floats2half2_rn(v.z, v.w);
    reinterpret_cast<__half2*>(g_feat16)[i * 2 + 0] = q0;
    reinterpret_cast<__half2*>(g_feat16)[i * 2 + 1] = q1;
}

__global__ void wprep_kernel(const float* __restrict__ Ws1, const float* __restrict__ Wn1,
                             const float* __restrict__ Ws2, const float* __restrict__ Wn2,
                             const float* __restrict__ Wo) {
    int i = blockIdx.x * blockDim.x + threadIdx.x;
    float v; __nv_bfloat16 *dh, *dl; int idx;
    if (i < 32768) {
        int n = i >> 8, k = i & 255;
        v = (k < 128) ? Ws1[k * 128 + n] : Wn1[(k - 128) * 128 + n];
        dh = g_B1_hi; dl = g_B1_lo; idx = i;
    } else if (i < 65536) {
        int j = i - 32768; int n = j >> 8, k = j & 255;
        v = (k < 128) ? Ws2[k * 128 + n] : Wn2[(k - 128) * 128 + n];
        dh = g_B2_hi; dl = g_B2_lo; idx = j;
    } else if (i < 73728) {
        int j = i - 65536; int n = j >> 7, k = j & 127;
        v = Wo[k * 64 + n];
        dh = g_Bo_hi; dl = g_Bo_lo; idx = j;
    } else return;
    __nv_bfloat16 h, l;
    split_bf16(v, h, l);
    dh[idx] = h; dl[idx] = l;
}

// ---------------- gather-mean (fp16 in, fp16 out): one warp per dst node ----
// Fully predicated: ALWAYS 8 row-loads in flight; out-of-range slots read
// valid (next node's / zero-pad) indices and are nulled by an fma mask.
__global__ __launch_bounds__(256)
void gather_kernel(const __half* __restrict__ h) {
    unsigned warp = (blockIdx.x * blockDim.x + threadIdx.x) >> 5;
    if (warp >= N_NODES) return;
    const unsigned lane = threadIdx.x & 31;
    unsigned start = g_off[warp];
    unsigned end   = g_off[warp + 1];

    float ax = 0.f, ay = 0.f, az = 0.f, aw = 0.f;
    const uint2* __restrict__ hv = reinterpret_cast<const uint2*>(h);
    for (unsigned i = start; i < end; i += 8) {
        int myi = 0;
        if (lane < 8) myi = __ldg(&g_esrc[i + lane]);     // coalesced; pad-safe
        uint2 u[8];
        float m[8];
#pragma unroll
        for (int q = 0; q < 8; ++q) {
            int s = __shfl_sync(0xffffffffu, myi, q);
            m[q] = (i + (unsigned)q < end) ? 1.f : 0.f;
            u[q] = __ldg(&hv[(size_t)s * 32 + lane]);
        }
#pragma unroll
        for (int q = 0; q < 8; ++q) {
            float2 f0 = __half22float2(*reinterpret_cast<__half2*>(&u[q].x));
            float2 f1 = __half22float2(*reinterpret_cast<__half2*>(&u[q].y));
            ax = fmaf(m[q], f0.x, ax);
            ay = fmaf(m[q], f0.y, ay);
            az = fmaf(m[q], f1.x, az);
            aw = fmaf(m[q], f1.y, aw);
        }
    }
    float sc = g_inv[warp];
    __half2 o0 = __floats2half2_rn(ax * sc, ay * sc);
    __half2 o1 = __floats2half2_rn(az * sc, aw * sc);
    uint2 o;
    o.x = *reinterpret_cast<uint32_t*>(&o0);
    o.y = *reinterpret_cast<uint32_t*>(&o1);
    reinterpret_cast<uint2*>(g_agg16)[(size_t)warp * 32 + lane] = o;
}

// ---------------- mma.sync split-bf16 GEMM, fp16 activations ----------------
// C[128 x BN] = sum over NCHUNKS chunks of 64 K-cols: Ah*Bh + Ah*Bl + Al*Bh
// A source fp16; split to bf16 hi/lo during smem staging (exact).
// DUALSRC: chunks 0-1 self (A16), chunks 2-3 neighbor (g_agg16).
// Software pipeline: prefetch next chunk's global data into regs during mma.
constexpr int ROWB = 144;                       // 64 bf16 (128B) + 16B pad
constexpr int smem_bytes(int BN) { return 2 * 128 * ROWB + 2 * BN * ROWB; }

template<int BN, int NCHUNKS, bool DUALSRC, bool WF32, bool WF16, bool RELU>
__global__ __launch_bounds__(512)
void mma_gemm_kernel(const __half* __restrict__ A16,
                     const __nv_bfloat16* __restrict__ B_hi,
                     const __nv_bfloat16* __restrict__ B_lo,
                     const float* __restrict__ bias,
                     float* __restrict__ outf,
                     __half* __restrict__ outh) {
    extern __shared__ unsigned char dynsm[];
    constexpr int OFF_A_HI = 0;
    constexpr int OFF_A_LO = 128 * ROWB;
    constexpr int OFF_B_HI = 2 * 128 * ROWB;
    constexpr int OFF_B_LO = OFF_B_HI + BN * ROWB;
    constexpr int KTOT = NCHUNKS * 64;
    constexpr int NW = BN / 32;                 // warps along N
    constexpr int NB_IT = BN * 8 / 512;         // B stage iters per thread

    const int tid  = threadIdx.x;
    const int wid  = tid >> 5;
    const int lane = tid & 31;
    const int rowBase = blockIdx.x * 128;
    const uint32_t sbase = smem_to_u32(dynsm);

    const bool active = wid < 4 * NW;
    const int warpM = wid / NW;
    const int warpN = wid % NW;

    float acc[2][4][4];
#pragma unroll
    for (int mi = 0; mi < 2; ++mi)
#pragma unroll
        for (int j = 0; j < 4; ++j)
#pragma unroll
            for (int c = 0; c < 4; ++c) acc[mi][j][c] = 0.f;

    const int lm_m = lane >> 3;
    const int lm_r = lane & 7;
    const int lm_rowoff = (lm_m & 1) * 8 + lm_r;
    const int lm_coloff = (lm_m >> 1) * 16;

    uint4 aRaw[2];
    uint4 bH[NB_IT], bL[NB_IT];

    auto load_chunk = [&](int ch) {
#pragma unroll
        for (int l = 0; l < 2; ++l) {
            int u = tid + l * 512;
            int r = u >> 3, c = u & 7;
            int gr = rowBase + r;
            uint4 v = make_uint4(0, 0, 0, 0);
            if (gr < N_NODES) {
                const __half* src = (!DUALSRC || ch < 2) ? A16 : g_agg16;
                int koff = (DUALSRC ? (ch & 1) : ch) * 64;
                v = *reinterpret_cast<const uint4*>(src + (size_t)gr * 128 + koff + c * 8);
            }
            aRaw[l] = v;
        }
#pragma unroll
        for (int l = 0; l < NB_IT; ++l) {
            int u = tid + l * 512;
            int n = u >> 3, c = u & 7;
            size_t off = (size_t)n * KTOT + ch * 64 + c * 8;
            bH[l] = *reinterpret_cast<const uint4*>(B_hi + off);
            bL[l] = *reinterpret_cast<const uint4*>(B_lo + off);
        }
    };
    auto store_chunk = [&]() {
#pragma unroll
        for (int l = 0; l < 2; ++l) {
            int u = tid + l * 512;
            int r = u >> 3, c = u & 7;
            uint4 hi4, lo4;
            cvt_h8_split(aRaw[l], hi4, lo4);
            *reinterpret_cast<uint4*>(dynsm + OFF_A_HI + r * ROWB + c * 16) = hi4;
            *reinterpret_cast<uint4*>(dynsm + OFF_A_LO + r * ROWB + c * 16) = lo4;
        }
#pragma unroll
        for (int l = 0; l < NB_IT; ++l) {
            int u = tid + l * 512;
            int n = u >> 3, c = u & 7;
            *reinterpret_cast<uint4*>(dynsm + OFF_B_HI + n * ROWB + c * 16) = bH[l];
            *reinterpret_cast<uint4*>(dynsm + OFF_B_LO + n * ROWB + c * 16) = bL[l];
        }
    };

    load_chunk(0);
    for (int ch = 0; ch < NCHUNKS; ++ch) {
        store_chunk();
        __syncthreads();
        if (ch + 1 < NCHUNKS) load_chunk(ch + 1);   // latency overlaps mma below

        if (active) {
#pragma unroll
            for (int ks = 0; ks < 4; ++ks) {
                const int kb = ks * 32 + lm_coloff;
                uint32_t ah[2][4], al[2][4];
#pragma unroll
                for (int mi = 0; mi < 2; ++mi) {
                    int row = warpM * 32 + mi * 16 + lm_rowoff;
                    ldsm_x4(sbase + OFF_A_HI + row * ROWB + kb, ah[mi]);
                    ldsm_x4(sbase + OFF_A_LO + row * ROWB + kb, al[mi]);
                }
                uint32_t bh[2][4], bl[2][4];
#pragma unroll
                for (int nb = 0; nb < 2; ++nb) {
                    int nrow = warpN * 32 + nb * 16 + lm_rowoff;
                    ldsm_x4(sbase + OFF_B_HI + nrow * ROWB + kb, bh[nb]);
                    ldsm_x4(sbase + OFF_B_LO + nrow * ROWB + kb, bl[nb]);
                }
#pragma unroll
                for (int mi = 0; mi < 2; ++mi)
#pragma unroll
                    for (int j = 0; j < 4; ++j) {
                        const int nb = j >> 1, jj = j & 1;
                        mma16816(acc[mi][j], ah[mi], bh[nb][jj], bh[nb][jj + 2]);
                        mma16816(acc[mi][j], ah[mi], bl[nb][jj], bl[nb][jj + 2]);
                        mma16816(acc[mi][j], al[mi], bh[nb][jj], bh[nb][jj + 2]);
                    }
            }
        }
        __syncthreads();
    }

    // ---- epilogue
    if (active) {
        const int rlo  = rowBase + warpM * 32 + (lane >> 2);
        const int colw = warpN * 32 + 2 * (lane & 3);
#pragma unroll
        for (int mi = 0; mi < 2; ++mi) {
#pragma unroll
            for (int j = 0; j < 4; ++j) {
                const int col = colw + j * 8;
                const float b0 = __ldg(&bias[col]);
                const float b1 = __ldg(&bias[col + 1]);
#pragma unroll
                for (int half = 0; half < 2; ++half) {
                    int r = rlo + mi * 16 + half * 8;
                    if (r >= N_NODES) continue;
                    float v0 = acc[mi][j][2 * half + 0] + b0;
                    float v1 = acc[mi][j][2 * half + 1] + b1;
                    if (RELU) { v0 = fmaxf(v0, 0.f); v1 = fmaxf(v1, 0.f); }
                    if (WF32) {
                        float2 f2; f2.x = v0; f2.y = v1;
                        *reinterpret_cast<float2*>(outf + (size_t)r * BN + col) = f2;
                    }
                    if (WF16) {
                        __half2 hh = __floats2half2_rn(v0, v1);
                        *reinterpret_cast<__half2*>(outh + (size_t)r * BN + col) = hh;
                    }
                }
            }
        }
    }
}

// ---------------- launch ----------------
extern "C" void kernel_launch(void* const* d_in, const int* in_sizes, int n_in,
                              void* d_out, int out_size) {
    const float* feat = (const float*)d_in[0];
    const int*   src  = (const int*)  d_in[1];
    const int*   dst  = (const int*)  d_in[2];
    const float* Ws1  = (const float*)d_in[3];
    const float* Wn1  = (const float*)d_in[4];
    const float* b1   = (const float*)d_in[5];
    const float* Ws2  = (const float*)d_in[6];
    const float* Wn2  = (const float*)d_in[7];
    const float* b2   = (const float*)d_in[8];
    const float* Wout = (const float*)d_in[9];
    const float* bout = (const float*)d_in[10];
    float* out = (float*)d_out;

    __half *p_feat16, *p_h1_16, *p_h2_16;
    __nv_bfloat16 *p_B1_hi, *p_B1_lo, *p_B2_hi, *p_B2_lo, *p_Bo_hi, *p_Bo_lo;
    cudaGetSymbolAddress((void**)&p_feat16, g_feat16);
    cudaGetSymbolAddress((void**)&p_h1_16, g_h1_16);
    cudaGetSymbolAddress((void**)&p_h2_16, g_h2_16);
    cudaGetSymbolAddress((void**)&p_B1_hi, g_B1_hi);
    cudaGetSymbolAddress((void**)&p_B1_lo, g_B1_lo);
    cudaGetSymbolAddress((void**)&p_B2_hi, g_B2_hi);
    cudaGetSymbolAddress((void**)&p_B2_lo, g_B2_lo);
    cudaGetSymbolAddress((void**)&p_Bo_hi, g_Bo_hi);
    cudaGetSymbolAddress((void**)&p_Bo_lo, g_Bo_lo);
    cudaFuncSetAttribute(mma_gemm_kernel<128, 4, true, false, true, true>,
                         cudaFuncAttributeMaxDynamicSharedMemorySize, smem_bytes(128));
    cudaFuncSetAttribute(mma_gemm_kernel<64, 2, false, true, false, false>,
                         cudaFuncAttributeMaxDynamicSharedMemorySize, smem_bytes(64));

    const int IB  = (N_NODES + 255) / 256;
    const int EB  = (N_EDGES + 255) / 256;
    const int GAB = (N_NODES * 32 + 255) / 256;
    const int GB  = (N_NODES + 127) / 128;               // 782

    // CSR build
    zero_ideg_kernel<<<IB, 256>>>();
    deg_kernel<<<EB, 256>>>(dst);
    scan_kernel<<<1, 1024>>>();
    fill_kernel<<<EB, 256>>>(src, dst);

    // prep
    wprep_kernel<<<288, 256>>>(Ws1, Wn1, Ws2, Wn2, Wout);
    fconv_kernel<<<GAB, 256>>>(feat);

    // layer 1
    gather_kernel<<<GAB, 256>>>(p_feat16);
    mma_gemm_kernel<128, 4, true, false, true, true>
        <<<GB, 512, smem_bytes(128)>>>(p_feat16, p_B1_hi, p_B1_lo, b1, nullptr, p_h1_16);

    // layer 2
    gather_kernel<<<GAB, 256>>>(p_h1_16);
    mma_gemm_kernel<128, 4, true, false, true, true>
        <<<GB, 512, smem_bytes(128)>>>(p_h1_16, p_B2_hi, p_B2_lo, b2, nullptr, p_h2_16);

    // output projection
    mma_gemm_kernel<64, 2, false, true, false, false>
        <<<GB, 512, smem_bytes(64)>>>(p_h2_16, p_Bo_hi, p_Bo_lo, bout, out, nullptr);
}

// round 11
// speedup vs baseline: 1.1569x; 1.1569x over previous
#include <cuda_runtime.h>
#include <cuda_bf16.h>
#include <cuda_fp16.h>
#include <cstdint>

#define N_NODES 100000
#define N_EDGES 1600000
#define D_IN 128
#define D_HID 128
#define N_CLASSES 64

// ---------------- device scratch (no dynamic alloc) ----------------
// Single fp16 copy of every activation.
__device__ __align__(16) __half g_feat16[(size_t)N_NODES * D_IN];
__device__ __align__(16) __half g_agg16 [(size_t)N_NODES * D_HID];
__device__ __align__(16) __half g_h1_16 [(size_t)N_NODES * D_HID];
__device__ __align__(16) __half g_h2_16 [(size_t)N_NODES * D_HID];
// transposed split weights (fp16 hi/lo, 22-bit effective mantissa), B[n][k]
__device__ __align__(16) __half g_B1_hi[128 * 256];
__device__ __align__(16) __half g_B1_lo[128 * 256];
__device__ __align__(16) __half g_B2_hi[128 * 256];
__device__ __align__(16) __half g_B2_lo[128 * 256];
__device__ __align__(16) __half g_Bo_hi[64 * 128];
__device__ __align__(16) __half g_Bo_lo[64 * 128];
// CSR
__device__ float    g_inv [N_NODES];
__device__ unsigned g_ideg[N_NODES];
__device__ unsigned g_off [N_NODES + 1];
__device__ unsigned g_cur [N_NODES];
__device__ int      g_esrc[N_EDGES];

// ---------------- helpers ----------------
__device__ __forceinline__ uint32_t smem_to_u32(const void* p) {
    uint32_t a;
    asm("{ .reg .u64 t; cvta.to.shared.u64 t, %1; cvt.u32.u64 %0, t; }" : "=r"(a) : "l"(p));
    return a;
}

__device__ __forceinline__ void ldsm_x4(uint32_t addr, uint32_t* r) {
    asm volatile("ldmatrix.sync.aligned.m8n8.x4.shared.b16 {%0,%1,%2,%3}, [%4];"
                 : "=r"(r[0]), "=r"(r[1]), "=r"(r[2]), "=r"(r[3]) : "r"(addr));
}

// fp16 x fp16 -> fp32 accumulate
__device__ __forceinline__ void mma16816h(float* c, const uint32_t* a,
                                          uint32_t b0, uint32_t b1) {
    asm volatile("mma.sync.aligned.m16n8k16.row.col.f32.f16.f16.f32 "
                 "{%0,%1,%2,%3}, {%4,%5,%6,%7}, {%8,%9}, {%0,%1,%2,%3};"
                 : "+f"(c[0]), "+f"(c[1]), "+f"(c[2]), "+f"(c[3])
                 : "r"(a[0]), "r"(a[1]), "r"(a[2]), "r"(a[3]), "r"(b0), "r"(b1));
}

__device__ __forceinline__ void split_fp16(float v, __half& hi, __half& lo) {
    hi = __float2half_rn(v);
    lo = __float2half_rn(v - __half2float(hi));
}

// ---------------- CSR build ----------------
__global__ void zero_ideg_kernel() {
    int i = blockIdx.x * blockDim.x + threadIdx.x;
    if (i < N_NODES) g_ideg[i] = 0u;
}
__global__ void deg_kernel(const int* __restrict__ dst) {
    int e = blockIdx.x * blockDim.x + threadIdx.x;
    if (e < N_EDGES) atomicAdd(&g_ideg[dst[e]], 1u);
}
__global__ __launch_bounds__(1024)
void scan_kernel() {
    __shared__ unsigned sm[1024];
    const int t  = threadIdx.x;
    const int CH = (N_NODES + 1023) / 1024;
    int lo = t * CH;
    int hi = lo + CH; if (hi > N_NODES) hi = N_NODES;
    if (lo > N_NODES) lo = N_NODES;
    unsigned sum = 0;
    for (int i = lo; i < hi; ++i) sum += g_ideg[i];
    sm[t] = sum;
    __syncthreads();
    for (int d = 1; d < 1024; d <<= 1) {
        unsigned u = (t >= d) ? sm[t - d] : 0u;
        __syncthreads();
        sm[t] += u;
        __syncthreads();
    }
    unsigned off = sm[t] - sum;
    for (int i = lo; i < hi; ++i) {
        unsigned d = g_ideg[i];
        g_off[i] = off;
        g_cur[i] = off;
        g_inv[i] = 1.0f / fmaxf((float)d, 1.0f);
        off += d;
    }
    if (t == 1023) g_off[N_NODES] = sm[1023];
}
__global__ void fill_kernel(const int* __restrict__ src, const int* __restrict__ dst) {
    int e = blockIdx.x * blockDim.x + threadIdx.x;
    if (e < N_EDGES) {
        unsigned p = atomicAdd(&g_cur[dst[e]], 1u);
        g_esrc[p] = src[e];
    }
}

// ---------------- input/weight prep ----------------
__global__ void fconv_kernel(const float* __restrict__ f) {
    unsigned i = blockIdx.x * blockDim.x + threadIdx.x;   // over N_NODES*32 float4 units
    if (i >= (unsigned)N_NODES * 32u) return;
    float4 v = reinterpret_cast<const float4*>(f)[i];
    __half2 q0 = __floats2half2_rn(v.x, v.y);
    __half2 q1 = __floats2half2_rn(v.z, v.w);
    reinterpret_cast<__half2*>(g_feat16)[i * 2 + 0] = q0;
    reinterpret_cast<__half2*>(g_feat16)[i * 2 + 1] = q1;
}

__global__ void wprep_kernel(const float* __restrict__ Ws1, const float* __restrict__ Wn1,
                             const float* __restrict__ Ws2, const float* __restrict__ Wn2,
                             const float* __restrict__ Wo) {
    int i = blockIdx.x * blockDim.x + threadIdx.x;
    float v; __half *dh, *dl; int idx;
    if (i < 32768) {
        int n = i >> 8, k = i & 255;
        v = (k < 128) ? Ws1[k * 128 + n] : Wn1[(k - 128) * 128 + n];
        dh = g_B1_hi; dl = g_B1_lo; idx = i;
    } else if (i < 65536) {
        int j = i - 32768; int n = j >> 8, k = j & 255;
        v = (k < 128) ? Ws2[k * 128 + n] : Wn2[(k - 128) * 128 + n];
        dh = g_B2_hi; dl = g_B2_lo; idx = j;
    } else if (i < 73728) {
        int j = i - 65536; int n = j >> 7, k = j & 127;
        v = Wo[k * 64 + n];
        dh = g_Bo_hi; dl = g_Bo_lo; idx = j;
    } else return;
    __half h, l;
    split_fp16(v, h, l);
    dh[idx] = h; dl[idx] = l;
}

// ---------------- gather-mean (fp16 in, fp16 out): one warp per dst node ----
// (R9 form — proven fastest)
__global__ __launch_bounds__(256)
void gather_kernel(const __half* __restrict__ h) {
    unsigned warp = (blockIdx.x * blockDim.x + threadIdx.x) >> 5;
    if (warp >= N_NODES) return;
    const unsigned lane = threadIdx.x & 31;
    unsigned start = g_off[warp];
    unsigned end   = g_off[warp + 1];

    float ax = 0.f, ay = 0.f, az = 0.f, aw = 0.f;
    const uint2* __restrict__ hv = reinterpret_cast<const uint2*>(h);
    unsigned i = start;
    for (; i + 8 <= end; i += 8) {
        uint2 u[8];
#pragma unroll
        for (int q = 0; q < 8; ++q) {
            int s = __ldg(&g_esrc[i + q]);
            u[q] = hv[(size_t)s * 32 + lane];
        }
#pragma unroll
        for (int q = 0; q < 8; ++q) {
            float2 f0 = __half22float2(*reinterpret_cast<__half2*>(&u[q].x));
            float2 f1 = __half22float2(*reinterpret_cast<__half2*>(&u[q].y));
            ax += f0.x; ay += f0.y; az += f1.x; aw += f1.y;
        }
    }
    for (; i < end; ++i) {
        int s = __ldg(&g_esrc[i]);
        uint2 u = hv[(size_t)s * 32 + lane];
        float2 f0 = __half22float2(*reinterpret_cast<__half2*>(&u.x));
        float2 f1 = __half22float2(*reinterpret_cast<__half2*>(&u.y));
        ax += f0.x; ay += f0.y; az += f1.x; aw += f1.y;
    }
    float sc = g_inv[warp];
    __half2 o0 = __floats2half2_rn(ax * sc, ay * sc);
    __half2 o1 = __floats2half2_rn(az * sc, aw * sc);
    uint2 o;
    o.x = *reinterpret_cast<uint32_t*>(&o0);
    o.y = *reinterpret_cast<uint32_t*>(&o1);
    reinterpret_cast<uint2*>(g_agg16)[(size_t)warp * 32 + lane] = o;
}

// ---------------- mma.sync fp16 2-term GEMM ----------------
// C[128 x BN] = sum over NCHUNKS chunks of 64 K-cols: A16*Bh + A16*Bl
// A fp16 staged raw; weight split fp16 hi/lo (22-bit effective).
// DUALSRC: chunks 0-1 self (A16), chunks 2-3 neighbor (g_agg16).
// Software pipeline: prefetch next chunk's global data into regs during mma.
constexpr int ROWB = 144;                       // 64 fp16 (128B) + 16B pad
constexpr int smem_bytes(int BN) { return 128 * ROWB + 2 * BN * ROWB; }

template<int BN, int NCHUNKS, bool DUALSRC, bool WF32, bool WF16, bool RELU>
__global__ __launch_bounds__(512)
void mma_gemm_kernel(const __half* __restrict__ A16,
                     const __half* __restrict__ B_hi,
                     const __half* __restrict__ B_lo,
                     const float* __restrict__ bias,
                     float* __restrict__ outf,
                     __half* __restrict__ outh) {
    extern __shared__ unsigned char dynsm[];
    constexpr int OFF_A    = 0;
    constexpr int OFF_B_HI = 128 * ROWB;
    constexpr int OFF_B_LO = OFF_B_HI + BN * ROWB;
    constexpr int KTOT = NCHUNKS * 64;
    constexpr int NW = BN / 32;                 // warps along N
    constexpr int NB_IT = BN * 8 / 512;         // B stage iters per thread

    const int tid  = threadIdx.x;
    const int wid  = tid >> 5;
    const int lane = tid & 31;
    const int rowBase = blockIdx.x * 128;
    const uint32_t sbase = smem_to_u32(dynsm);

    const bool active = wid < 4 * NW;
    const int warpM = wid / NW;
    const int warpN = wid % NW;

    float acc[2][4][4];
#pragma unroll
    for (int mi = 0; mi < 2; ++mi)
#pragma unroll
        for (int j = 0; j < 4; ++j)
#pragma unroll
            for (int c = 0; c < 4; ++c) acc[mi][j][c] = 0.f;

    const int lm_m = lane >> 3;
    const int lm_r = lane & 7;
    const int lm_rowoff = (lm_m & 1) * 8 + lm_r;
    const int lm_coloff = (lm_m >> 1) * 16;

    uint4 aRaw[2];
    uint4 bH[NB_IT], bL[NB_IT];

    auto load_chunk = [&](int ch) {
#pragma unroll
        for (int l = 0; l < 2; ++l) {
            int u = tid + l * 512;
            int r = u >> 3, c = u & 7;
            int gr = rowBase + r;
            uint4 v = make_uint4(0, 0, 0, 0);
            if (gr < N_NODES) {
                const __half* src = (!DUALSRC || ch < 2) ? A16 : g_agg16;
                int koff = (DUALSRC ? (ch & 1) : ch) * 64;
                v = *reinterpret_cast<const uint4*>(src + (size_t)gr * 128 + koff + c * 8);
            }
            aRaw[l] = v;
        }
#pragma unroll
        for (int l = 0; l < NB_IT; ++l) {
            int u = tid + l * 512;
            int n = u >> 3, c = u & 7;
            size_t off = (size_t)n * KTOT + ch * 64 + c * 8;
            bH[l] = *reinterpret_cast<const uint4*>(B_hi + off);
            bL[l] = *reinterpret_cast<const uint4*>(B_lo + off);
        }
    };
    auto store_chunk = [&]() {
#pragma unroll
        for (int l = 0; l < 2; ++l) {
            int u = tid + l * 512;
            int r = u >> 3, c = u & 7;
            *reinterpret_cast<uint4*>(dynsm + OFF_A + r * ROWB + c * 16) = aRaw[l];
        }
#pragma unroll
        for (int l = 0; l < NB_IT; ++l) {
            int u = tid + l * 512;
            int n = u >> 3, c = u & 7;
            *reinterpret_cast<uint4*>(dynsm + OFF_B_HI + n * ROWB + c * 16) = bH[l];
            *reinterpret_cast<uint4*>(dynsm + OFF_B_LO + n * ROWB + c * 16) = bL[l];
        }
    };

    load_chunk(0);
    for (int ch = 0; ch < NCHUNKS; ++ch) {
        store_chunk();
        __syncthreads();
        if (ch + 1 < NCHUNKS) load_chunk(ch + 1);   // latency overlaps mma below

        if (active) {
#pragma unroll
            for (int ks = 0; ks < 4; ++ks) {
                const int kb = ks * 32 + lm_coloff;
                uint32_t ah[2][4];
#pragma unroll
                for (int mi = 0; mi < 2; ++mi) {
                    int row = warpM * 32 + mi * 16 + lm_rowoff;
                    ldsm_x4(sbase + OFF_A + row * ROWB + kb, ah[mi]);
                }
                uint32_t bh[2][4], bl[2][4];
#pragma unroll
                for (int nb = 0; nb < 2; ++nb) {
                    int nrow = warpN * 32 + nb * 16 + lm_rowoff;
                    ldsm_x4(sbase + OFF_B_HI + nrow * ROWB + kb, bh[nb]);
                    ldsm_x4(sbase + OFF_B_LO + nrow * ROWB + kb, bl[nb]);
                }
#pragma unroll
                for (int mi = 0; mi < 2; ++mi)
#pragma unroll
                    for (int j = 0; j < 4; ++j) {
                        const int nb = j >> 1, jj = j & 1;
                        mma16816h(acc[mi][j], ah[mi], bh[nb][jj], bh[nb][jj + 2]);
                        mma16816h(acc[mi][j], ah[mi], bl[nb][jj], bl[nb][jj + 2]);
                    }
            }
        }
        __syncthreads();
    }

    // ---- epilogue
    if (active) {
        const int rlo  = rowBase + warpM * 32 + (lane >> 2);
        const int colw = warpN * 32 + 2 * (lane & 3);
#pragma unroll
        for (int mi = 0; mi < 2; ++mi) {
#pragma unroll
            for (int j = 0; j < 4; ++j) {
                const int col = colw + j * 8;
                const float b0 = __ldg(&bias[col]);
                const float b1 = __ldg(&bias[col + 1]);
#pragma unroll
                for (int half = 0; half < 2; ++half) {
                    int r = rlo + mi * 16 + half * 8;
                    if (r >= N_NODES) continue;
                    float v0 = acc[mi][j][2 * half + 0] + b0;
                    float v1 = acc[mi][j][2 * half + 1] + b1;
                    if (RELU) { v0 = fmaxf(v0, 0.f); v1 = fmaxf(v1, 0.f); }
                    if (WF32) {
                        float2 f2; f2.x = v0; f2.y = v1;
                        *reinterpret_cast<float2*>(outf + (size_t)r * BN + col) = f2;
                    }
                    if (WF16) {
                        __half2 hh = __floats2half2_rn(v0, v1);
                        *reinterpret_cast<__half2*>(outh + (size_t)r * BN + col) = hh;
                    }
                }
            }
        }
    }
}

// ---------------- launch ----------------
extern "C" void kernel_launch(void* const* d_in, const int* in_sizes, int n_in,
                              void* d_out, int out_size) {
    const float* feat = (const float*)d_in[0];
    const int*   src  = (const int*)  d_in[1];
    const int*   dst  = (const int*)  d_in[2];
    const float* Ws1  = (const float*)d_in[3];
    const float* Wn1  = (const float*)d_in[4];
    const float* b1   = (const float*)d_in[5];
    const float* Ws2  = (const float*)d_in[6];
    const float* Wn2  = (const float*)d_in[7];
    const float* b2   = (const float*)d_in[8];
    const float* Wout = (const float*)d_in[9];
    const float* bout = (const float*)d_in[10];
    float* out = (float*)d_out;

    __half *p_feat16, *p_h1_16, *p_h2_16;
    __half *p_B1_hi, *p_B1_lo, *p_B2_hi, *p_B2_lo, *p_Bo_hi, *p_Bo_lo;
    cudaGetSymbolAddress((void**)&p_feat16, g_feat16);
    cudaGetSymbolAddress((void**)&p_h1_16, g_h1_16);
    cudaGetSymbolAddress((void**)&p_h2_16, g_h2_16);
    cudaGetSymbolAddress((void**)&p_B1_hi, g_B1_hi);
    cudaGetSymbolAddress((void**)&p_B1_lo, g_B1_lo);
    cudaGetSymbolAddress((void**)&p_B2_hi, g_B2_hi);
    cudaGetSymbolAddress((void**)&p_B2_lo, g_B2_lo);
    cudaGetSymbolAddress((void**)&p_Bo_hi, g_Bo_hi);
    cudaGetSymbolAddress((void**)&p_Bo_lo, g_Bo_lo);
    cudaFuncSetAttribute(mma_gemm_kernel<128, 4, true, false, true, true>,
                         cudaFuncAttributeMaxDynamicSharedMemorySize, smem_bytes(128));
    cudaFuncSetAttribute(mma_gemm_kernel<64, 2, false, true, false, false>,
                         cudaFuncAttributeMaxDynamicSharedMemorySize, smem_bytes(64));

    const int IB  = (N_NODES + 255) / 256;
    const int EB  = (N_EDGES + 255) / 256;
    const int GAB = (N_NODES * 32 + 255) / 256;
    const int GB  = (N_NODES + 127) / 128;               // 782

    // CSR build
    zero_ideg_kernel<<<IB, 256>>>();
    deg_kernel<<<EB, 256>>>(dst);
    scan_kernel<<<1, 1024>>>();
    fill_kernel<<<EB, 256>>>(src, dst);

    // prep
    wprep_kernel<<<288, 256>>>(Ws1, Wn1, Ws2, Wn2, Wout);
    fconv_kernel<<<GAB, 256>>>(feat);

    // layer 1
    gather_kernel<<<GAB, 256>>>(p_feat16);
    mma_gemm_kernel<128, 4, true, false, true, true>
        <<<GB, 512, smem_bytes(128)>>>(p_feat16, p_B1_hi, p_B1_lo, b1, nullptr, p_h1_16);

    // layer 2
    gather_kernel<<<GAB, 256>>>(p_h1_16);
    mma_gemm_kernel<128, 4, true, false, true, true>
        <<<GB, 512, smem_bytes(128)>>>(p_h1_16, p_B2_hi, p_B2_lo, b2, nullptr, p_h2_16);

    // output projection
    mma_gemm_kernel<64, 2, false, true, false, false>
        <<<GB, 512, smem_bytes(64)>>>(p_h2_16, p_Bo_hi, p_Bo_lo, bout, out, nullptr);
}